// round 11
// baseline (speedup 1.0000x reference)
#include <cuda_runtime.h>
#include <cuda_bf16.h>
#include <math.h>
#include <stdint.h>

// Problem constants
#define NH 1024
#define NF 4096
#define NE 8
#define NG 9                  // 8 experts + shared fallback
#define NTOK 4096
#define CAPE 512
#define MT 128                // M tile
#define NTILE 128             // N tile
#define KC 32                 // K chunk per stage
#define NSTAGE 3
#define MAXTILES 64

// stage layout (bytes):
//   A: [128 m][32 k] bf16, row pitch 80B (64B data + 16B pad) -> conflict-free ldsm
//   B: [32 k][128 n] bf16, row pitch 256B, chunk swizzle ch^(k&7)
#define A_HI 0
#define A_LO 10240
#define B_HI 20480
#define B_LO 28672
#define STAGE_BYTES 36864
#define SMEMSZ (1024 + NSTAGE*STAGE_BYTES)

typedef __nv_bfloat16 bf16;

// ---------------- static device scratch ----------------
__device__ __align__(16) bf16 g_xhi[(size_t)NTOK * NH];   // [token][k]
__device__ __align__(16) bf16 g_xlo[(size_t)NTOK * NH];
__device__ __align__(16) bf16 g_w1hi[(size_t)NG * NH * NF]; // [g][k=H][n=F]
__device__ __align__(16) bf16 g_w1lo[(size_t)NG * NH * NF];
__device__ __align__(16) bf16 g_w2hi[(size_t)NG * NF * NH]; // [g][k=F][n=H]
__device__ __align__(16) bf16 g_w2lo[(size_t)NG * NF * NH];
__device__ __align__(16) bf16 g_hhi[(size_t)NTOK * NF];   // [grouped row][k]
__device__ __align__(16) bf16 g_hlo[(size_t)NTOK * NF];
__device__ int g_prim[NTOK];
__device__ int g_sec[NTOK];
__device__ int g_gather[NTOK];
__device__ int g_goff[NG + 1];
__device__ int g_ntiles;
__device__ int g_tile_group[MAXTILES];
__device__ int g_tile_row[MAXTILES];

// ---------------- helpers ----------------
__device__ __forceinline__ uint32_t smem_u32(const void* p) {
    uint32_t a;
    asm("{ .reg .u64 t; cvta.to.shared.u64 t, %1; cvt.u32.u64 %0, t; }" : "=r"(a) : "l"(p));
    return a;
}
__device__ __forceinline__ void cpasync16(uint32_t s, const void* g) {
    asm volatile("cp.async.cg.shared.global [%0], [%1], 16;" :: "r"(s), "l"(g) : "memory");
}
__device__ __forceinline__ void ldm4(uint32_t* r, uint32_t addr) {
    asm volatile("ldmatrix.sync.aligned.m8n8.x4.shared.b16 {%0,%1,%2,%3}, [%4];"
                 : "=r"(r[0]), "=r"(r[1]), "=r"(r[2]), "=r"(r[3]) : "r"(addr));
}
__device__ __forceinline__ void ldm4t(uint32_t* r, uint32_t addr) {
    asm volatile("ldmatrix.sync.aligned.m8n8.x4.trans.shared.b16 {%0,%1,%2,%3}, [%4];"
                 : "=r"(r[0]), "=r"(r[1]), "=r"(r[2]), "=r"(r[3]) : "r"(addr));
}
__device__ __forceinline__ void mma16816(float* d, const uint32_t* a, uint32_t b0, uint32_t b1) {
    asm volatile(
        "mma.sync.aligned.m16n8k16.row.col.f32.bf16.bf16.f32 "
        "{%0,%1,%2,%3}, {%4,%5,%6,%7}, {%8,%9}, {%0,%1,%2,%3};"
        : "+f"(d[0]), "+f"(d[1]), "+f"(d[2]), "+f"(d[3])
        : "r"(a[0]), "r"(a[1]), "r"(a[2]), "r"(a[3]), "r"(b0), "r"(b1));
}
// A-tile: 80B pitch, chunk ch in [0,4); bank-quad = (5*row + ch) mod 8 -> conflict-free
__device__ __forceinline__ uint32_t swA(int row, int ch) {
    return (uint32_t)(row * 80 + ch * 16);
}
// B-tile: 256B pitch, 16 x 16B chunks/row, xor swizzle (conflict-free for trans reads)
__device__ __forceinline__ uint32_t swB(int krow, int ch) {
    return (uint32_t)((krow * 16 + (ch ^ (krow & 7))) << 4);
}
__device__ __forceinline__ void split2(float v, bf16& h, bf16& l) {
    h = __float2bfloat16(v);
    l = __float2bfloat16(v - __bfloat162float(h));
}
__device__ __forceinline__ uint32_t pack2(bf16 a, bf16 b) {
    return (uint32_t)__bfloat16_as_ushort(a) | ((uint32_t)__bfloat16_as_ushort(b) << 16);
}

// ---------------------------------------------------------------------------
// Router + x split conversion fused (x hi/lo stored in TOKEN order)
// ---------------------------------------------------------------------------
__global__ __launch_bounds__(256) void router_kernel(
    const float* __restrict__ x, const float* __restrict__ rw,
    const float* __restrict__ rb)
{
    int n = blockIdx.x;
    __shared__ float s_log[NE];
    int tid = threadIdx.x;
    int wid = tid >> 5, lane = tid & 31;
    const float* xr = x + (size_t)n * NH;

    {
        float4 v = ((const float4*)xr)[tid];
        bf16 h0, h1, h2, h3, l0, l1, l2, l3;
        split2(v.x, h0, l0); split2(v.y, h1, l1);
        split2(v.z, h2, l2); split2(v.w, h3, l3);
        ((uint2*)(g_xhi + (size_t)n * NH))[tid] = make_uint2(pack2(h0, h1), pack2(h2, h3));
        ((uint2*)(g_xlo + (size_t)n * NH))[tid] = make_uint2(pack2(l0, l1), pack2(l2, l3));
    }

    const float* wr = rw + (size_t)wid * NH;
    float s = 0.f;
    #pragma unroll 8
    for (int k = lane; k < NH; k += 32) s += xr[k] * wr[k];
    #pragma unroll
    for (int o = 16; o; o >>= 1) s += __shfl_xor_sync(0xffffffffu, s, o);
    if (lane == 0) s_log[wid] = s + rb[wid];
    __syncthreads();
    if (tid == 0) {
        float b0 = -INFINITY; int i0 = 0;
        #pragma unroll
        for (int e = 0; e < NE; e++) { float v = s_log[e]; if (v > b0) { b0 = v; i0 = e; } }
        float b1 = -INFINITY; int i1 = 0;
        #pragma unroll
        for (int e = 0; e < NE; e++) { if (e == i0) continue; float v = s_log[e]; if (v > b1) { b1 = v; i1 = e; } }
        g_prim[n] = i0; g_sec[n] = i1;
    }
}

// ---------------------------------------------------------------------------
// Capacity assignment (exact reference semantics)
// ---------------------------------------------------------------------------
__global__ __launch_bounds__(320) void assign_kernel()
{
    __shared__ unsigned char s_prim[NTOK], s_sec[NTOK], s_keep[NTOK], s_assign[NTOK];
    __shared__ int s_used[NE], s_gcnt[NG], s_goff[NG + 1];
    int tid = threadIdx.x;
    int wid = tid >> 5, lane = tid & 31;
    unsigned lmask = (1u << lane) - 1u;

    for (int t = tid; t < NTOK; t += blockDim.x) {
        s_prim[t] = (unsigned char)g_prim[t];
        s_sec[t]  = (unsigned char)g_sec[t];
    }
    __syncthreads();

    if (wid < NE) {
        int e = wid, run = 0;
        for (int c = 0; c < NTOK; c += 32) {
            int t = c + lane;
            bool bit = (s_prim[t] == e);
            unsigned m = __ballot_sync(0xffffffffu, bit);
            if (bit) {
                int pos = run + __popc(m & lmask);
                bool keep = pos < CAPE;
                s_keep[t]   = keep ? 1 : 0;
                s_assign[t] = keep ? (unsigned char)e : (unsigned char)255;
            }
            run += __popc(m);
        }
        if (lane == 0) s_used[e] = run < CAPE ? run : CAPE;
    }
    __syncthreads();

    if (wid < NE) {
        int e = wid, run = 0, used = s_used[e];
        for (int c = 0; c < NTOK; c += 32) {
            int t = c + lane;
            bool bit = (s_sec[t] == e) && (s_keep[t] == 0);
            unsigned m = __ballot_sync(0xffffffffu, bit);
            if (bit) {
                int pos2 = run + __popc(m & lmask);
                bool take2 = (used + pos2) < CAPE;
                s_assign[t] = take2 ? (unsigned char)e : (unsigned char)8;
            }
            run += __popc(m);
        }
    }
    __syncthreads();

    if (wid < NG) {
        int g = wid, run = 0;
        for (int c = 0; c < NTOK; c += 32) {
            int t = c + lane;
            unsigned m = __ballot_sync(0xffffffffu, s_assign[t] == g);
            run += __popc(m);
        }
        if (lane == 0) s_gcnt[g] = run;
    }
    __syncthreads();

    if (tid == 0) {
        s_goff[0] = 0;
        for (int g = 0; g < NG; g++) s_goff[g + 1] = s_goff[g] + s_gcnt[g];
        int nt = 0;
        for (int g = 0; g < NG; g++)
            for (int r = s_goff[g]; r < s_goff[g + 1]; r += MT) {
                g_tile_group[nt] = g; g_tile_row[nt] = r; nt++;
            }
        g_ntiles = nt;
        for (int g = 0; g <= NG; g++) g_goff[g] = s_goff[g];
    }
    __syncthreads();

    if (wid < NG) {
        int g = wid, run = 0, base = s_goff[g];
        for (int c = 0; c < NTOK; c += 32) {
            int t = c + lane;
            bool bit = (s_assign[t] == g);
            unsigned m = __ballot_sync(0xffffffffu, bit);
            if (bit) g_gather[base + run + __popc(m & lmask)] = t;
            run += __popc(m);
        }
    }
}

// ---------------------------------------------------------------------------
// Streaming weight conversion (both w1 and w2 in one launch)
// ---------------------------------------------------------------------------
__global__ __launch_bounds__(256) void convert_w_kernel(
    const float* __restrict__ W1e, const float* __restrict__ W1f,
    const float* __restrict__ W2e, const float* __restrict__ W2f)
{
    const size_t perg = (size_t)NH * NF;
    int g = blockIdx.z;
    bool w1sel = (blockIdx.y == 0);
    const float* We = w1sel ? W1e : W2e;
    const float* Wf = w1sel ? W1f : W2f;
    const float4* src = (const float4*)((g < NE) ? (We + (size_t)g * perg) : Wf);
    uint2* dh = (uint2*)((w1sel ? g_w1hi : g_w2hi) + (size_t)g * perg);
    uint2* dl = (uint2*)((w1sel ? g_w1lo : g_w2lo) + (size_t)g * perg);
    size_t n4 = perg / 4;
    for (size_t i = blockIdx.x * 256 + threadIdx.x; i < n4; i += (size_t)gridDim.x * 256) {
        float4 v = src[i];
        bf16 h0, h1, h2, h3, l0, l1, l2, l3;
        split2(v.x, h0, l0); split2(v.y, h1, l1);
        split2(v.z, h2, l2); split2(v.w, h3, l3);
        dh[i] = make_uint2(pack2(h0, h1), pack2(h2, h3));
        dl[i] = make_uint2(pack2(l0, l1), pack2(l2, l3));
    }
}

// ---------------------------------------------------------------------------
// Grouped GEMM on mma.sync bf16 (3-pass hi/lo split), 128x128 tile, 8 warps,
// 3-stage cp.async pipeline, 2 CTAs/SM, conflict-free A, pass-major MMA order.
// ---------------------------------------------------------------------------
template<int KDIM, int NDIM, bool FIRST>
__global__ __launch_bounds__(256, 2) void moe_gemm_mma(
    const float* __restrict__ BiasE, const float* __restrict__ BiasF,
    float* __restrict__ Cout)
{
    constexpr int NCH = KDIM / KC;
    extern __shared__ __align__(1024) char smem[];

    int tileIdx = blockIdx.y;
    if (tileIdx >= g_ntiles) return;
    int tid = threadIdx.x, wid = tid >> 5, lane = tid & 31;
    int g    = g_tile_group[tileIdx];
    int row0 = g_tile_row[tileIdx];
    int rend = g_goff[g + 1];
    int n0   = blockIdx.x * NTILE;
    const float* bias = (g < NE) ? (BiasE + (size_t)g * NDIM) : BiasF;

    const bf16* Ahi = FIRST ? g_xhi : g_hhi;
    const bf16* Alo = FIRST ? g_xlo : g_hlo;
    const bf16* Bhi = (FIRST ? g_w1hi : g_w2hi) + (size_t)g * KDIM * NDIM;
    const bf16* Blo = (FIRST ? g_w1lo : g_w2lo) + (size_t)g * KDIM * NDIM;

    int*   s_rows = (int*)smem;            // 128 ints
    float* s_bias = (float*)(smem + 512);  // 128 floats
    uint32_t stage0 = smem_u32(smem) + 1024;

    if (tid < MT) {
        int r = row0 + tid;
        s_rows[tid] = (r < NTOK) ? g_gather[r] : 0;
        s_bias[tid] = bias[n0 + tid];
    }
    __syncthreads();

    auto load_stage = [&](int s, int c) {
        uint32_t st = stage0 + s * STAGE_BYTES;
        int k0 = c * KC;
        #pragma unroll
        for (int i = tid; i < 1024; i += 256) {          // A hi|lo: 512 chunks each
            int buf = i >> 9, idx = i & 511;
            int row = idx >> 2, ch = idx & 3;
            int ar;
            if (FIRST) ar = s_rows[row];                 // token index
            else { ar = row0 + row; if (ar >= NTOK) ar = NTOK - 1; }
            const bf16* src = (buf ? Alo : Ahi) + (size_t)ar * KDIM + k0 + ch * 8;
            cpasync16(st + (buf ? A_LO : A_HI) + swA(row, ch), src);
        }
        #pragma unroll
        for (int i = tid; i < 1024; i += 256) {          // B hi|lo: [32 k][128 n]
            int buf = i >> 9, idx = i & 511;
            int kr = idx >> 4, ch = idx & 15;
            const bf16* src = (buf ? Blo : Bhi) + (size_t)(k0 + kr) * NDIM + n0 + ch * 8;
            cpasync16(st + (buf ? B_LO : B_HI) + swB(kr, ch), src);
        }
        asm volatile("cp.async.commit_group;" ::: "memory");
    };

    load_stage(0, 0);
    load_stage(1, 1);

    int wm = (wid >> 2) * 64;   // warp M offset
    int wn = (wid & 3) * 32;    // warp N offset

    // B ldmatrix.trans lane addressing
    int grp = lane >> 3, rit = lane & 7;
    int b_kadd = (grp & 1) * 8 + rit;
    int b_nsub = (grp >> 1) * 8;
    int a_r16 = lane & 15, a_chsel = lane >> 4;

    float d[4][4][4];
    #pragma unroll
    for (int a = 0; a < 4; a++)
        #pragma unroll
        for (int b = 0; b < 4; b++)
            #pragma unroll
            for (int c = 0; c < 4; c++) d[a][b][c] = 0.f;

    for (int c = 0; c < NCH; c++) {
        asm volatile("cp.async.wait_group 1;" ::: "memory");
        __syncthreads();
        if (c + 2 < NCH) load_stage((c + 2) % NSTAGE, c + 2);
        else asm volatile("cp.async.commit_group;" ::: "memory");

        uint32_t st = stage0 + (c % NSTAGE) * STAGE_BYTES;
        #pragma unroll
        for (int s = 0; s < 2; s++) {
            uint32_t bh[2][4], bl[2][4];
            int kl = s * 16 + b_kadd;
            #pragma unroll
            for (int nt = 0; nt < 2; nt++) {
                int nch = (wn + nt * 16 + b_nsub) >> 3;
                uint32_t off = swB(kl, nch);
                ldm4t(bh[nt], st + B_HI + off);
                ldm4t(bl[nt], st + B_LO + off);
            }
            int ach = s * 2 + a_chsel;
            #pragma unroll
            for (int mt = 0; mt < 4; mt++) {
                uint32_t ah[4], al[4];
                int row = wm + mt * 16 + a_r16;
                uint32_t off = swA(row, ach);
                ldm4(ah, st + A_HI + off);
                ldm4(al, st + A_LO + off);
                // pass-major ordering: each accumulator's successive MMAs are
                // 4 issues apart -> RAW distance covers HMMA latency
                #pragma unroll
                for (int j = 0; j < 4; j++) {
                    int nt = j >> 1, sl = j & 1;
                    mma16816(d[mt][j], ah, bh[nt][sl * 2], bh[nt][sl * 2 + 1]);
                }
                #pragma unroll
                for (int j = 0; j < 4; j++) {
                    int nt = j >> 1, sl = j & 1;
                    mma16816(d[mt][j], ah, bl[nt][sl * 2], bl[nt][sl * 2 + 1]);
                }
                #pragma unroll
                for (int j = 0; j < 4; j++) {
                    int nt = j >> 1, sl = j & 1;
                    mma16816(d[mt][j], al, bh[nt][sl * 2], bh[nt][sl * 2 + 1]);
                }
            }
        }
    }

    // epilogue
    int r4 = lane >> 2, c2 = (lane & 3) * 2;
    #pragma unroll
    for (int mt = 0; mt < 4; mt++) {
        #pragma unroll
        for (int half = 0; half < 2; half++) {
            int lr = wm + mt * 16 + r4 + half * 8;
            int grow = row0 + lr;
            if (grow >= rend) continue;
            int tok = s_rows[lr];
            #pragma unroll
            for (int j = 0; j < 4; j++) {
                int col = wn + j * 8 + c2;
                float v0 = d[mt][j][half * 2 + 0] + s_bias[col];
                float v1 = d[mt][j][half * 2 + 1] + s_bias[col + 1];
                if (FIRST) {
                    v0 = 0.5f * v0 * (1.0f + erff(v0 * 0.70710678118654752440f));
                    v1 = 0.5f * v1 * (1.0f + erff(v1 * 0.70710678118654752440f));
                    bf16 h0, h1, l0, l1;
                    split2(v0, h0, l0); split2(v1, h1, l1);
                    *(uint32_t*)(g_hhi + (size_t)grow * NDIM + n0 + col) = pack2(h0, h1);
                    *(uint32_t*)(g_hlo + (size_t)grow * NDIM + n0 + col) = pack2(l0, l1);
                } else {
                    *(float2*)(Cout + (size_t)tok * NDIM + n0 + col) = make_float2(v0, v1);
                }
            }
        }
    }
}

// ---------------------------------------------------------------------------
extern "C" void kernel_launch(void* const* d_in, const int* in_sizes, int n_in,
                              void* d_out, int out_size)
{
    const float* x   = (const float*)d_in[0];
    const float* rw  = (const float*)d_in[1];
    const float* rb  = (const float*)d_in[2];
    const float* w1  = (const float*)d_in[3];
    const float* b1  = (const float*)d_in[4];
    const float* w2  = (const float*)d_in[5];
    const float* b2  = (const float*)d_in[6];
    const float* sw1 = (const float*)d_in[7];
    const float* sb1 = (const float*)d_in[8];
    const float* sw2 = (const float*)d_in[9];
    const float* sb2 = (const float*)d_in[10];
    float* out = (float*)d_out;

    cudaFuncSetAttribute(moe_gemm_mma<NH, NF, true>,
                         cudaFuncAttributeMaxDynamicSharedMemorySize, SMEMSZ);
    cudaFuncSetAttribute(moe_gemm_mma<NF, NH, false>,
                         cudaFuncAttributeMaxDynamicSharedMemorySize, SMEMSZ);

    router_kernel<<<NTOK, 256>>>(x, rw, rb);
    assign_kernel<<<1, 320>>>();
    convert_w_kernel<<<dim3(512, 2, NG), 256>>>(w1, sw1, w2, sw2);
    // GEMM1: grouped x @ w1 -> gelu -> g_h (hi/lo)
    moe_gemm_mma<NH, NF, true ><<<dim3(NF / NTILE, 41), 256, SMEMSZ>>>(b1, sb1, nullptr);
    // GEMM2: g_h @ w2 -> scatter to out
    moe_gemm_mma<NF, NH, false><<<dim3(NH / NTILE, 41), 256, SMEMSZ>>>(b2, sb2, out);
}

// round 12
// speedup vs baseline: 1.0746x; 1.0746x over previous
#include <cuda_runtime.h>
#include <cuda_bf16.h>
#include <math.h>
#include <stdint.h>

// Problem constants
#define NH 1024
#define NF 4096
#define NE 8
#define NG 9                  // 8 experts + shared fallback
#define NTOK 4096
#define CAPE 512
#define MT 128                // M tile
#define NTILE 128             // N tile
#define KC 32                 // K chunk per stage
#define NSTAGE 3
#define TILE_Y 41             // max GEMM tile rows in grid.y
#define CVB_W 576             // converter blocks: 64 per group x 9 groups

// stage layout (bytes): Ahi | Alo | Bhi | Blo, each 8KB  (R7-proven layout)
//   A: [128 m][32 k] bf16, row pitch 64B, chunk swizzle ch^(row&3)
//   B: [32 k][128 n] bf16, row pitch 256B, chunk swizzle ch^(k&7)
#define A_HI 0
#define A_LO 8192
#define B_HI 16384
#define B_LO 24576
#define STAGE_BYTES 32768
#define SMEMSZ (1024 + NSTAGE*STAGE_BYTES)

typedef __nv_bfloat16 bf16;

// ---------------- static device scratch ----------------
__device__ __align__(16) bf16 g_xhi[(size_t)NTOK * NH];   // [token][k]
__device__ __align__(16) bf16 g_xlo[(size_t)NTOK * NH];
__device__ __align__(16) bf16 g_w1hi[(size_t)NG * NH * NF]; // [g][k=H][n=F]
__device__ __align__(16) bf16 g_w1lo[(size_t)NG * NH * NF];
__device__ __align__(16) bf16 g_w2hi[(size_t)NG * NF * NH]; // [g][k=F][n=H]
__device__ __align__(16) bf16 g_w2lo[(size_t)NG * NF * NH];
__device__ __align__(16) bf16 g_hhi[(size_t)NTOK * NF];   // [grouped row][k]
__device__ __align__(16) bf16 g_hlo[(size_t)NTOK * NF];
__device__ int g_prim[NTOK];
__device__ int g_sec[NTOK];
__device__ int g_gather[NTOK];
__device__ int g_goff[NG + 1];
__device__ int g_ntiles;
__device__ int g_tile_group[64];
__device__ int g_tile_row[64];

// ---------------- helpers ----------------
__device__ __forceinline__ uint32_t smem_u32(const void* p) {
    uint32_t a;
    asm("{ .reg .u64 t; cvta.to.shared.u64 t, %1; cvt.u32.u64 %0, t; }" : "=r"(a) : "l"(p));
    return a;
}
__device__ __forceinline__ void cpasync16(uint32_t s, const void* g) {
    asm volatile("cp.async.cg.shared.global [%0], [%1], 16;" :: "r"(s), "l"(g) : "memory");
}
__device__ __forceinline__ void ldm4(uint32_t* r, uint32_t addr) {
    asm volatile("ldmatrix.sync.aligned.m8n8.x4.shared.b16 {%0,%1,%2,%3}, [%4];"
                 : "=r"(r[0]), "=r"(r[1]), "=r"(r[2]), "=r"(r[3]) : "r"(addr));
}
__device__ __forceinline__ void ldm4t(uint32_t* r, uint32_t addr) {
    asm volatile("ldmatrix.sync.aligned.m8n8.x4.trans.shared.b16 {%0,%1,%2,%3}, [%4];"
                 : "=r"(r[0]), "=r"(r[1]), "=r"(r[2]), "=r"(r[3]) : "r"(addr));
}
__device__ __forceinline__ void mma16816(float* d, const uint32_t* a, uint32_t b0, uint32_t b1) {
    asm volatile(
        "mma.sync.aligned.m16n8k16.row.col.f32.bf16.bf16.f32 "
        "{%0,%1,%2,%3}, {%4,%5,%6,%7}, {%8,%9}, {%0,%1,%2,%3};"
        : "+f"(d[0]), "+f"(d[1]), "+f"(d[2]), "+f"(d[3])
        : "r"(a[0]), "r"(a[1]), "r"(a[2]), "r"(a[3]), "r"(b0), "r"(b1));
}
// A-tile swizzle: 64B rows, 4 x 16B chunks/row (R7 layout)
__device__ __forceinline__ uint32_t swA(int row, int ch) {
    return (uint32_t)((row * 4 + (ch ^ (row & 3))) << 4);
}
// B-tile swizzle: 256B rows, 16 x 16B chunks/row
__device__ __forceinline__ uint32_t swB(int krow, int ch) {
    return (uint32_t)((krow * 16 + (ch ^ (krow & 7))) << 4);
}
__device__ __forceinline__ void split2(float v, bf16& h, bf16& l) {
    h = __float2bfloat16(v);
    l = __float2bfloat16(v - __bfloat162float(h));
}
__device__ __forceinline__ uint32_t pack2(bf16 a, bf16 b) {
    return (uint32_t)__bfloat16_as_ushort(a) | ((uint32_t)__bfloat16_as_ushort(b) << 16);
}

// Streaming fp32 -> bf16 hi/lo conversion of one 1/64 slice of one group's weights.
// cvb in [0, CVB_W): group = cvb>>6, block-within-group = cvb&63.
__device__ void convert_slice(const float* __restrict__ We, const float* __restrict__ Wf,
                              bf16* __restrict__ Dh, bf16* __restrict__ Dl,
                              int cvb, int tid)
{
    const size_t perg = (size_t)NH * NF;
    int g = cvb >> 6;
    int bid = cvb & 63;
    const float4* src = (const float4*)((g < NE) ? (We + (size_t)g * perg) : Wf);
    uint2* dh = (uint2*)(Dh + (size_t)g * perg);
    uint2* dl = (uint2*)(Dl + (size_t)g * perg);
    size_t n4 = perg / 4;
    for (size_t i = (size_t)bid * 256 + tid; i < n4; i += (size_t)64 * 256) {
        float4 v = src[i];
        bf16 h0, h1, h2, h3, l0, l1, l2, l3;
        split2(v.x, h0, l0); split2(v.y, h1, l1);
        split2(v.z, h2, l2); split2(v.w, h3, l3);
        dh[i] = make_uint2(pack2(h0, h1), pack2(h2, h3));
        dl[i] = make_uint2(pack2(l0, l1), pack2(l2, l3));
    }
}

// ---------------------------------------------------------------------------
// Router + x split conversion + (fused) w1 conversion.
// blocks [0, NTOK): router per token; blocks [NTOK, NTOK+CVB_W): convert w1.
// ---------------------------------------------------------------------------
__global__ __launch_bounds__(256) void router_kernel(
    const float* __restrict__ x, const float* __restrict__ rw,
    const float* __restrict__ rb,
    const float* __restrict__ W1e, const float* __restrict__ W1f)
{
    if (blockIdx.x >= NTOK) {
        convert_slice(W1e, W1f, g_w1hi, g_w1lo, blockIdx.x - NTOK, threadIdx.x);
        return;
    }
    int n = blockIdx.x;
    __shared__ float s_log[NE];
    int tid = threadIdx.x;
    int wid = tid >> 5, lane = tid & 31;
    const float* xr = x + (size_t)n * NH;

    {
        float4 v = ((const float4*)xr)[tid];
        bf16 h0, h1, h2, h3, l0, l1, l2, l3;
        split2(v.x, h0, l0); split2(v.y, h1, l1);
        split2(v.z, h2, l2); split2(v.w, h3, l3);
        ((uint2*)(g_xhi + (size_t)n * NH))[tid] = make_uint2(pack2(h0, h1), pack2(h2, h3));
        ((uint2*)(g_xlo + (size_t)n * NH))[tid] = make_uint2(pack2(l0, l1), pack2(l2, l3));
    }

    const float* wr = rw + (size_t)wid * NH;
    float s = 0.f;
    #pragma unroll 8
    for (int k = lane; k < NH; k += 32) s += xr[k] * wr[k];
    #pragma unroll
    for (int o = 16; o; o >>= 1) s += __shfl_xor_sync(0xffffffffu, s, o);
    if (lane == 0) s_log[wid] = s + rb[wid];
    __syncthreads();
    if (tid == 0) {
        float b0 = -INFINITY; int i0 = 0;
        #pragma unroll
        for (int e = 0; e < NE; e++) { float v = s_log[e]; if (v > b0) { b0 = v; i0 = e; } }
        float b1 = -INFINITY; int i1 = 0;
        #pragma unroll
        for (int e = 0; e < NE; e++) { if (e == i0) continue; float v = s_log[e]; if (v > b1) { b1 = v; i1 = e; } }
        g_prim[n] = i0; g_sec[n] = i1;
    }
}

// ---------------------------------------------------------------------------
// Capacity assignment (exact reference semantics)
// ---------------------------------------------------------------------------
__global__ __launch_bounds__(320) void assign_kernel()
{
    __shared__ unsigned char s_prim[NTOK], s_sec[NTOK], s_keep[NTOK], s_assign[NTOK];
    __shared__ int s_used[NE], s_gcnt[NG], s_goff[NG + 1];
    int tid = threadIdx.x;
    int wid = tid >> 5, lane = tid & 31;
    unsigned lmask = (1u << lane) - 1u;

    for (int t = tid; t < NTOK; t += blockDim.x) {
        s_prim[t] = (unsigned char)g_prim[t];
        s_sec[t]  = (unsigned char)g_sec[t];
    }
    __syncthreads();

    if (wid < NE) {
        int e = wid, run = 0;
        for (int c = 0; c < NTOK; c += 32) {
            int t = c + lane;
            bool bit = (s_prim[t] == e);
            unsigned m = __ballot_sync(0xffffffffu, bit);
            if (bit) {
                int pos = run + __popc(m & lmask);
                bool keep = pos < CAPE;
                s_keep[t]   = keep ? 1 : 0;
                s_assign[t] = keep ? (unsigned char)e : (unsigned char)255;
            }
            run += __popc(m);
        }
        if (lane == 0) s_used[e] = run < CAPE ? run : CAPE;
    }
    __syncthreads();

    if (wid < NE) {
        int e = wid, run = 0, used = s_used[e];
        for (int c = 0; c < NTOK; c += 32) {
            int t = c + lane;
            bool bit = (s_sec[t] == e) && (s_keep[t] == 0);
            unsigned m = __ballot_sync(0xffffffffu, bit);
            if (bit) {
                int pos2 = run + __popc(m & lmask);
                bool take2 = (used + pos2) < CAPE;
                s_assign[t] = take2 ? (unsigned char)e : (unsigned char)8;
            }
            run += __popc(m);
        }
    }
    __syncthreads();

    if (wid < NG) {
        int g = wid, run = 0;
        for (int c = 0; c < NTOK; c += 32) {
            int t = c + lane;
            unsigned m = __ballot_sync(0xffffffffu, s_assign[t] == g);
            run += __popc(m);
        }
        if (lane == 0) s_gcnt[g] = run;
    }
    __syncthreads();

    if (tid == 0) {
        s_goff[0] = 0;
        for (int g = 0; g < NG; g++) s_goff[g + 1] = s_goff[g] + s_gcnt[g];
        int nt = 0;
        for (int g = 0; g < NG; g++)
            for (int r = s_goff[g]; r < s_goff[g + 1]; r += MT) {
                g_tile_group[nt] = g; g_tile_row[nt] = r; nt++;
            }
        g_ntiles = nt;
        for (int g = 0; g <= NG; g++) g_goff[g] = s_goff[g];
    }
    __syncthreads();

    if (wid < NG) {
        int g = wid, run = 0, base = s_goff[g];
        for (int c = 0; c < NTOK; c += 32) {
            int t = c + lane;
            bool bit = (s_assign[t] == g);
            unsigned m = __ballot_sync(0xffffffffu, bit);
            if (bit) g_gather[base + run + __popc(m & lmask)] = t;
            run += __popc(m);
        }
    }
}

// ---------------------------------------------------------------------------
// Grouped GEMM on mma.sync bf16 (3-pass hi/lo split), 128x128 tile, 8 warps,
// 3-stage cp.async pipeline, 2 CTAs/SM (exact R7 mainloop).
// FIRST=true additionally carries fused w2 conversion blocks at blockIdx.y>=TILE_Y
// (they fill GEMM1's tail wave with DRAM-bound work).
// ---------------------------------------------------------------------------
template<int KDIM, int NDIM, bool FIRST>
__global__ __launch_bounds__(256, 2) void moe_gemm_mma(
    const float* __restrict__ BiasE, const float* __restrict__ BiasF,
    float* __restrict__ Cout,
    const float* __restrict__ CWe, const float* __restrict__ CWf)
{
    constexpr int NCH = KDIM / KC;
    extern __shared__ __align__(1024) char smem[];

    if (FIRST && blockIdx.y >= TILE_Y) {
        int cvb = (blockIdx.y - TILE_Y) * 32 + blockIdx.x;   // 18*32 = 576
        if (cvb < CVB_W) convert_slice(CWe, CWf, g_w2hi, g_w2lo, cvb, threadIdx.x);
        return;
    }

    int tileIdx = blockIdx.y;
    if (tileIdx >= g_ntiles) return;
    int tid = threadIdx.x, wid = tid >> 5, lane = tid & 31;
    int g    = g_tile_group[tileIdx];
    int row0 = g_tile_row[tileIdx];
    int rend = g_goff[g + 1];
    int n0   = blockIdx.x * NTILE;
    const float* bias = (g < NE) ? (BiasE + (size_t)g * NDIM) : BiasF;

    const bf16* Ahi = FIRST ? g_xhi : g_hhi;
    const bf16* Alo = FIRST ? g_xlo : g_hlo;
    const bf16* Bhi = (FIRST ? g_w1hi : g_w2hi) + (size_t)g * KDIM * NDIM;
    const bf16* Blo = (FIRST ? g_w1lo : g_w2lo) + (size_t)g * KDIM * NDIM;

    int*   s_rows = (int*)smem;            // 128 ints
    float* s_bias = (float*)(smem + 512);  // 128 floats
    uint32_t stage0 = smem_u32(smem) + 1024;

    if (tid < MT) {
        int r = row0 + tid;
        s_rows[tid] = (r < NTOK) ? g_gather[r] : 0;
        s_bias[tid] = bias[n0 + tid];
    }
    __syncthreads();

    auto load_stage = [&](int s, int c) {
        uint32_t st = stage0 + s * STAGE_BYTES;
        int k0 = c * KC;
        #pragma unroll
        for (int i = tid; i < 1024; i += 256) {          // A hi|lo: 512 chunks each
            int buf = i >> 9, idx = i & 511;
            int row = idx >> 2, ch = idx & 3;
            int ar;
            if (FIRST) ar = s_rows[row];                 // token index
            else { ar = row0 + row; if (ar >= NTOK) ar = NTOK - 1; }
            const bf16* src = (buf ? Alo : Ahi) + (size_t)ar * KDIM + k0 + ch * 8;
            cpasync16(st + (buf ? A_LO : A_HI) + swA(row, ch), src);
        }
        #pragma unroll
        for (int i = tid; i < 1024; i += 256) {          // B hi|lo: [32 k][128 n]
            int buf = i >> 9, idx = i & 511;
            int kr = idx >> 4, ch = idx & 15;
            const bf16* src = (buf ? Blo : Bhi) + (size_t)(k0 + kr) * NDIM + n0 + ch * 8;
            cpasync16(st + (buf ? B_LO : B_HI) + swB(kr, ch), src);
        }
        asm volatile("cp.async.commit_group;" ::: "memory");
    };

    load_stage(0, 0);
    load_stage(1, 1);

    int wm = (wid >> 2) * 64;   // warp M offset
    int wn = (wid & 3) * 32;    // warp N offset

    // B ldmatrix.trans lane addressing
    int grp = lane >> 3, rit = lane & 7;
    int b_kadd = (grp & 1) * 8 + rit;
    int b_nsub = (grp >> 1) * 8;
    int a_r16 = lane & 15, a_chsel = lane >> 4;

    float d[4][4][4];
    #pragma unroll
    for (int a = 0; a < 4; a++)
        #pragma unroll
        for (int b = 0; b < 4; b++)
            #pragma unroll
            for (int c = 0; c < 4; c++) d[a][b][c] = 0.f;

    for (int c = 0; c < NCH; c++) {
        asm volatile("cp.async.wait_group 1;" ::: "memory");
        __syncthreads();
        if (c + 2 < NCH) load_stage((c + 2) % NSTAGE, c + 2);
        else asm volatile("cp.async.commit_group;" ::: "memory");

        uint32_t st = stage0 + (c % NSTAGE) * STAGE_BYTES;
        #pragma unroll
        for (int s = 0; s < 2; s++) {
            uint32_t bh[2][4], bl[2][4];
            int kl = s * 16 + b_kadd;
            #pragma unroll
            for (int nt = 0; nt < 2; nt++) {
                int nch = (wn + nt * 16 + b_nsub) >> 3;
                uint32_t off = swB(kl, nch);
                ldm4t(bh[nt], st + B_HI + off);
                ldm4t(bl[nt], st + B_LO + off);
            }
            int ach = s * 2 + a_chsel;
            #pragma unroll
            for (int mt = 0; mt < 4; mt++) {
                uint32_t ah[4], al[4];
                int row = wm + mt * 16 + a_r16;
                uint32_t off = swA(row, ach);
                ldm4(ah, st + A_HI + off);
                ldm4(al, st + A_LO + off);
                #pragma unroll
                for (int j = 0; j < 4; j++) {
                    int nt = j >> 1, sl = j & 1;
                    mma16816(d[mt][j], ah, bh[nt][sl * 2], bh[nt][sl * 2 + 1]);
                    mma16816(d[mt][j], ah, bl[nt][sl * 2], bl[nt][sl * 2 + 1]);
                    mma16816(d[mt][j], al, bh[nt][sl * 2], bh[nt][sl * 2 + 1]);
                }
            }
        }
    }

    // epilogue
    int r4 = lane >> 2, c2 = (lane & 3) * 2;
    #pragma unroll
    for (int mt = 0; mt < 4; mt++) {
        #pragma unroll
        for (int half = 0; half < 2; half++) {
            int lr = wm + mt * 16 + r4 + half * 8;
            int grow = row0 + lr;
            if (grow >= rend) continue;
            int tok = s_rows[lr];
            #pragma unroll
            for (int j = 0; j < 4; j++) {
                int col = wn + j * 8 + c2;
                float v0 = d[mt][j][half * 2 + 0] + s_bias[col];
                float v1 = d[mt][j][half * 2 + 1] + s_bias[col + 1];
                if (FIRST) {
                    v0 = 0.5f * v0 * (1.0f + erff(v0 * 0.70710678118654752440f));
                    v1 = 0.5f * v1 * (1.0f + erff(v1 * 0.70710678118654752440f));
                    bf16 h0, h1, l0, l1;
                    split2(v0, h0, l0); split2(v1, h1, l1);
                    *(uint32_t*)(g_hhi + (size_t)grow * NDIM + n0 + col) = pack2(h0, h1);
                    *(uint32_t*)(g_hlo + (size_t)grow * NDIM + n0 + col) = pack2(l0, l1);
                } else {
                    *(float2*)(Cout + (size_t)tok * NDIM + n0 + col) = make_float2(v0, v1);
                }
            }
        }
    }
}

// ---------------------------------------------------------------------------
extern "C" void kernel_launch(void* const* d_in, const int* in_sizes, int n_in,
                              void* d_out, int out_size)
{
    const float* x   = (const float*)d_in[0];
    const float* rw  = (const float*)d_in[1];
    const float* rb  = (const float*)d_in[2];
    const float* w1  = (const float*)d_in[3];
    const float* b1  = (const float*)d_in[4];
    const float* w2  = (const float*)d_in[5];
    const float* b2  = (const float*)d_in[6];
    const float* sw1 = (const float*)d_in[7];
    const float* sb1 = (const float*)d_in[8];
    const float* sw2 = (const float*)d_in[9];
    const float* sb2 = (const float*)d_in[10];
    float* out = (float*)d_out;

    cudaFuncSetAttribute(moe_gemm_mma<NH, NF, true>,
                         cudaFuncAttributeMaxDynamicSharedMemorySize, SMEMSZ);
    cudaFuncSetAttribute(moe_gemm_mma<NF, NH, false>,
                         cudaFuncAttributeMaxDynamicSharedMemorySize, SMEMSZ);

    // router + x split + fused w1 conversion (runs concurrently with routing)
    router_kernel<<<NTOK + CVB_W, 256>>>(x, rw, rb, w1, sw1);
    assign_kernel<<<1, 320>>>();
    // GEMM1 (+ fused w2 conversion filling the tail wave): x @ w1 -> gelu -> g_h
    moe_gemm_mma<NH, NF, true ><<<dim3(NF / NTILE, TILE_Y + 18), 256, SMEMSZ>>>(
        b1, sb1, nullptr, w2, sw2);
    // GEMM2: g_h @ w2 -> scatter to out
    moe_gemm_mma<NF, NH, false><<<dim3(NH / NTILE, TILE_Y), 256, SMEMSZ>>>(
        b2, sb2, out, nullptr, nullptr);
}

// round 13
// speedup vs baseline: 1.3809x; 1.2850x over previous
#include <cuda_runtime.h>
#include <cuda_fp16.h>
#include <math.h>
#include <stdint.h>

// Problem constants
#define NH 1024
#define NF 4096
#define NE 8
#define NG 9                  // 8 experts + shared fallback
#define NTOK 4096
#define CAPE 512
#define MT 128                // M tile
#define NTILE 128             // N tile
#define KC 32                 // K chunk per stage
#define NSTAGE 3
#define TILE_Y 41             // max GEMM tile rows in grid.y
#define CVB_W 576             // converter blocks: 64 per group x 9 groups
#define WSCALE 1024.0f        // weight pre-scale (power of 2)
#define INV_WSCALE 0.0009765625f

// stage layout (bytes): Ahi | Alo | B, each 8KB
//   A: [128 m][32 k] f16, row pitch 64B, chunk swizzle ch^(row&3)
//   B: [32 k][128 n] f16, row pitch 256B, chunk swizzle ch^(k&7)
#define A_HI 0
#define A_LO 8192
#define B_OFF 16384
#define STAGE_BYTES 24576
#define SMEMSZ (1024 + NSTAGE*STAGE_BYTES)

typedef __half f16;

// ---------------- static device scratch ----------------
__device__ __align__(16) f16 g_xhi[(size_t)NTOK * NH];   // [token][k]
__device__ __align__(16) f16 g_xlo[(size_t)NTOK * NH];
__device__ __align__(16) f16 g_w1[(size_t)NG * NH * NF]; // [g][k=H][n=F], x1024
__device__ __align__(16) f16 g_w2[(size_t)NG * NF * NH]; // [g][k=F][n=H], x1024
__device__ __align__(16) f16 g_hhi[(size_t)NTOK * NF];   // [grouped row][k]
__device__ __align__(16) f16 g_hlo[(size_t)NTOK * NF];
__device__ int g_prim[NTOK];
__device__ int g_sec[NTOK];
__device__ int g_gather[NTOK];
__device__ int g_goff[NG + 1];
__device__ int g_ntiles;
__device__ int g_tile_group[64];
__device__ int g_tile_row[64];

// ---------------- helpers ----------------
__device__ __forceinline__ uint32_t smem_u32(const void* p) {
    uint32_t a;
    asm("{ .reg .u64 t; cvta.to.shared.u64 t, %1; cvt.u32.u64 %0, t; }" : "=r"(a) : "l"(p));
    return a;
}
__device__ __forceinline__ void cpasync16(uint32_t s, const void* g) {
    asm volatile("cp.async.cg.shared.global [%0], [%1], 16;" :: "r"(s), "l"(g) : "memory");
}
__device__ __forceinline__ void ldm4(uint32_t* r, uint32_t addr) {
    asm volatile("ldmatrix.sync.aligned.m8n8.x4.shared.b16 {%0,%1,%2,%3}, [%4];"
                 : "=r"(r[0]), "=r"(r[1]), "=r"(r[2]), "=r"(r[3]) : "r"(addr));
}
__device__ __forceinline__ void ldm4t(uint32_t* r, uint32_t addr) {
    asm volatile("ldmatrix.sync.aligned.m8n8.x4.trans.shared.b16 {%0,%1,%2,%3}, [%4];"
                 : "=r"(r[0]), "=r"(r[1]), "=r"(r[2]), "=r"(r[3]) : "r"(addr));
}
__device__ __forceinline__ void mma16816(float* d, const uint32_t* a, uint32_t b0, uint32_t b1) {
    asm volatile(
        "mma.sync.aligned.m16n8k16.row.col.f32.f16.f16.f32 "
        "{%0,%1,%2,%3}, {%4,%5,%6,%7}, {%8,%9}, {%0,%1,%2,%3};"
        : "+f"(d[0]), "+f"(d[1]), "+f"(d[2]), "+f"(d[3])
        : "r"(a[0]), "r"(a[1]), "r"(a[2]), "r"(a[3]), "r"(b0), "r"(b1));
}
// A-tile swizzle: 64B rows, 4 x 16B chunks/row
__device__ __forceinline__ uint32_t swA(int row, int ch) {
    return (uint32_t)((row * 4 + (ch ^ (row & 3))) << 4);
}
// B-tile swizzle: 256B rows, 16 x 16B chunks/row
__device__ __forceinline__ uint32_t swB(int krow, int ch) {
    return (uint32_t)((krow * 16 + (ch ^ (krow & 7))) << 4);
}
__device__ __forceinline__ void split2h(float v, f16& h, f16& l) {
    h = __float2half_rn(v);
    l = __float2half_rn(v - __half2float(h));
}
__device__ __forceinline__ uint32_t pack2h(f16 a, f16 b) {
    return (uint32_t)__half_as_ushort(a) | ((uint32_t)__half_as_ushort(b) << 16);
}

// Streaming fp32 -> fp16 (x1024) conversion of one 1/64 slice of one group's weights.
__device__ void convert_slice(const float* __restrict__ We, const float* __restrict__ Wf,
                              f16* __restrict__ Dst, int cvb, int tid)
{
    const size_t perg = (size_t)NH * NF;
    int g = cvb >> 6;
    int bid = cvb & 63;
    const float4* src = (const float4*)((g < NE) ? (We + (size_t)g * perg) : Wf);
    uint2* dh = (uint2*)(Dst + (size_t)g * perg);
    size_t n4 = perg / 4;
    for (size_t i = (size_t)bid * 256 + tid; i < n4; i += (size_t)64 * 256) {
        float4 v = src[i];
        f16 h0 = __float2half_rn(v.x * WSCALE);
        f16 h1 = __float2half_rn(v.y * WSCALE);
        f16 h2 = __float2half_rn(v.z * WSCALE);
        f16 h3 = __float2half_rn(v.w * WSCALE);
        dh[i] = make_uint2(pack2h(h0, h1), pack2h(h2, h3));
    }
}

// ---------------------------------------------------------------------------
// Router + x split conversion + (fused) w1 conversion.
// ---------------------------------------------------------------------------
__global__ __launch_bounds__(256) void router_kernel(
    const float* __restrict__ x, const float* __restrict__ rw,
    const float* __restrict__ rb,
    const float* __restrict__ W1e, const float* __restrict__ W1f)
{
    if (blockIdx.x >= NTOK) {
        convert_slice(W1e, W1f, g_w1, blockIdx.x - NTOK, threadIdx.x);
        return;
    }
    int n = blockIdx.x;
    __shared__ float s_log[NE];
    int tid = threadIdx.x;
    int wid = tid >> 5, lane = tid & 31;
    const float* xr = x + (size_t)n * NH;

    {
        float4 v = ((const float4*)xr)[tid];
        f16 h0, h1, h2, h3, l0, l1, l2, l3;
        split2h(v.x, h0, l0); split2h(v.y, h1, l1);
        split2h(v.z, h2, l2); split2h(v.w, h3, l3);
        ((uint2*)(g_xhi + (size_t)n * NH))[tid] = make_uint2(pack2h(h0, h1), pack2h(h2, h3));
        ((uint2*)(g_xlo + (size_t)n * NH))[tid] = make_uint2(pack2h(l0, l1), pack2h(l2, l3));
    }

    const float* wr = rw + (size_t)wid * NH;
    float s = 0.f;
    #pragma unroll 8
    for (int k = lane; k < NH; k += 32) s += xr[k] * wr[k];
    #pragma unroll
    for (int o = 16; o; o >>= 1) s += __shfl_xor_sync(0xffffffffu, s, o);
    if (lane == 0) s_log[wid] = s + rb[wid];
    __syncthreads();
    if (tid == 0) {
        float b0 = -INFINITY; int i0 = 0;
        #pragma unroll
        for (int e = 0; e < NE; e++) { float v = s_log[e]; if (v > b0) { b0 = v; i0 = e; } }
        float b1 = -INFINITY; int i1 = 0;
        #pragma unroll
        for (int e = 0; e < NE; e++) { if (e == i0) continue; float v = s_log[e]; if (v > b1) { b1 = v; i1 = e; } }
        g_prim[n] = i0; g_sec[n] = i1;
    }
}

// ---------------------------------------------------------------------------
// Capacity assignment (exact reference semantics)
// ---------------------------------------------------------------------------
__global__ __launch_bounds__(320) void assign_kernel()
{
    __shared__ unsigned char s_prim[NTOK], s_sec[NTOK], s_keep[NTOK], s_assign[NTOK];
    __shared__ int s_used[NE], s_gcnt[NG], s_goff[NG + 1];
    int tid = threadIdx.x;
    int wid = tid >> 5, lane = tid & 31;
    unsigned lmask = (1u << lane) - 1u;

    for (int t = tid; t < NTOK; t += blockDim.x) {
        s_prim[t] = (unsigned char)g_prim[t];
        s_sec[t]  = (unsigned char)g_sec[t];
    }
    __syncthreads();

    if (wid < NE) {
        int e = wid, run = 0;
        for (int c = 0; c < NTOK; c += 32) {
            int t = c + lane;
            bool bit = (s_prim[t] == e);
            unsigned m = __ballot_sync(0xffffffffu, bit);
            if (bit) {
                int pos = run + __popc(m & lmask);
                bool keep = pos < CAPE;
                s_keep[t]   = keep ? 1 : 0;
                s_assign[t] = keep ? (unsigned char)e : (unsigned char)255;
            }
            run += __popc(m);
        }
        if (lane == 0) s_used[e] = run < CAPE ? run : CAPE;
    }
    __syncthreads();

    if (wid < NE) {
        int e = wid, run = 0, used = s_used[e];
        for (int c = 0; c < NTOK; c += 32) {
            int t = c + lane;
            bool bit = (s_sec[t] == e) && (s_keep[t] == 0);
            unsigned m = __ballot_sync(0xffffffffu, bit);
            if (bit) {
                int pos2 = run + __popc(m & lmask);
                bool take2 = (used + pos2) < CAPE;
                s_assign[t] = take2 ? (unsigned char)e : (unsigned char)8;
            }
            run += __popc(m);
        }
    }
    __syncthreads();

    if (wid < NG) {
        int g = wid, run = 0;
        for (int c = 0; c < NTOK; c += 32) {
            int t = c + lane;
            unsigned m = __ballot_sync(0xffffffffu, s_assign[t] == g);
            run += __popc(m);
        }
        if (lane == 0) s_gcnt[g] = run;
    }
    __syncthreads();

    if (tid == 0) {
        s_goff[0] = 0;
        for (int g = 0; g < NG; g++) s_goff[g + 1] = s_goff[g] + s_gcnt[g];
        int nt = 0;
        for (int g = 0; g < NG; g++)
            for (int r = s_goff[g]; r < s_goff[g + 1]; r += MT) {
                g_tile_group[nt] = g; g_tile_row[nt] = r; nt++;
            }
        g_ntiles = nt;
        for (int g = 0; g <= NG; g++) g_goff[g] = s_goff[g];
    }
    __syncthreads();

    if (wid < NG) {
        int g = wid, run = 0, base = s_goff[g];
        for (int c = 0; c < NTOK; c += 32) {
            int t = c + lane;
            bool bit = (s_assign[t] == g);
            unsigned m = __ballot_sync(0xffffffffu, bit);
            if (bit) g_gather[base + run + __popc(m & lmask)] = t;
            run += __popc(m);
        }
    }
}

// ---------------------------------------------------------------------------
// Grouped GEMM on mma.sync f16, 2-pass A-split, 128x128 tile, 8 warps,
// 3-stage cp.async pipeline, 2 CTAs/SM. Weights pre-scaled x1024.
// FIRST=true also carries fused w2 conversion blocks at blockIdx.y>=TILE_Y.
// ---------------------------------------------------------------------------
template<int KDIM, int NDIM, bool FIRST>
__global__ __launch_bounds__(256, 2) void moe_gemm_mma(
    const float* __restrict__ BiasE, const float* __restrict__ BiasF,
    float* __restrict__ Cout,
    const float* __restrict__ CWe, const float* __restrict__ CWf)
{
    constexpr int NCH = KDIM / KC;
    extern __shared__ __align__(1024) char smem[];

    if (FIRST && blockIdx.y >= TILE_Y) {
        int cvb = (blockIdx.y - TILE_Y) * 32 + blockIdx.x;   // 18*32 = 576
        if (cvb < CVB_W) convert_slice(CWe, CWf, g_w2, cvb, threadIdx.x);
        return;
    }

    int tileIdx = blockIdx.y;
    if (tileIdx >= g_ntiles) return;
    int tid = threadIdx.x, wid = tid >> 5, lane = tid & 31;
    int g    = g_tile_group[tileIdx];
    int row0 = g_tile_row[tileIdx];
    int rend = g_goff[g + 1];
    int n0   = blockIdx.x * NTILE;
    const float* bias = (g < NE) ? (BiasE + (size_t)g * NDIM) : BiasF;

    const f16* Ahi = FIRST ? g_xhi : g_hhi;
    const f16* Alo = FIRST ? g_xlo : g_hlo;
    const f16* B   = (FIRST ? g_w1 : g_w2) + (size_t)g * KDIM * NDIM;

    int*   s_rows = (int*)smem;            // 128 ints
    float* s_bias = (float*)(smem + 512);  // 128 floats
    uint32_t stage0 = smem_u32(smem) + 1024;

    if (tid < MT) {
        int r = row0 + tid;
        s_rows[tid] = (r < NTOK) ? g_gather[r] : 0;
        s_bias[tid] = bias[n0 + tid];
    }
    __syncthreads();

    auto load_stage = [&](int s, int c) {
        uint32_t st = stage0 + s * STAGE_BYTES;
        int k0 = c * KC;
        #pragma unroll
        for (int i = tid; i < 1024; i += 256) {          // A hi|lo: 512 chunks each
            int buf = i >> 9, idx = i & 511;
            int row = idx >> 2, ch = idx & 3;
            int ar;
            if (FIRST) ar = s_rows[row];                 // token index
            else { ar = row0 + row; if (ar >= NTOK) ar = NTOK - 1; }
            const f16* src = (buf ? Alo : Ahi) + (size_t)ar * KDIM + k0 + ch * 8;
            cpasync16(st + (buf ? A_LO : A_HI) + swA(row, ch), src);
        }
        #pragma unroll
        for (int i = tid; i < 512; i += 256) {           // B: [32 k][128 n]
            int kr = i >> 4, ch = i & 15;
            const f16* src = B + (size_t)(k0 + kr) * NDIM + n0 + ch * 8;
            cpasync16(st + B_OFF + swB(kr, ch), src);
        }
        asm volatile("cp.async.commit_group;" ::: "memory");
    };

    load_stage(0, 0);
    load_stage(1, 1);

    int wm = (wid >> 2) * 64;   // warp M offset
    int wn = (wid & 3) * 32;    // warp N offset

    // B ldmatrix.trans lane addressing
    int grp = lane >> 3, rit = lane & 7;
    int b_kadd = (grp & 1) * 8 + rit;
    int b_nsub = (grp >> 1) * 8;
    int a_r16 = lane & 15, a_chsel = lane >> 4;

    float d[4][4][4];
    #pragma unroll
    for (int a = 0; a < 4; a++)
        #pragma unroll
        for (int b = 0; b < 4; b++)
            #pragma unroll
            for (int c = 0; c < 4; c++) d[a][b][c] = 0.f;

    for (int c = 0; c < NCH; c++) {
        asm volatile("cp.async.wait_group 1;" ::: "memory");
        __syncthreads();
        if (c + 2 < NCH) load_stage((c + 2) % NSTAGE, c + 2);
        else asm volatile("cp.async.commit_group;" ::: "memory");

        uint32_t st = stage0 + (c % NSTAGE) * STAGE_BYTES;
        #pragma unroll
        for (int s = 0; s < 2; s++) {
            uint32_t bh[2][4];
            int kl = s * 16 + b_kadd;
            #pragma unroll
            for (int nt = 0; nt < 2; nt++) {
                int nch = (wn + nt * 16 + b_nsub) >> 3;
                ldm4t(bh[nt], st + B_OFF + swB(kl, nch));
            }
            int ach = s * 2 + a_chsel;
            #pragma unroll
            for (int mt = 0; mt < 4; mt++) {
                uint32_t ah[4], al[4];
                int row = wm + mt * 16 + a_r16;
                uint32_t off = swA(row, ach);
                ldm4(ah, st + A_HI + off);
                ldm4(al, st + A_LO + off);
                #pragma unroll
                for (int j = 0; j < 4; j++) {
                    int nt = j >> 1, sl = j & 1;
                    mma16816(d[mt][j], ah, bh[nt][sl * 2], bh[nt][sl * 2 + 1]);
                    mma16816(d[mt][j], al, bh[nt][sl * 2], bh[nt][sl * 2 + 1]);
                }
            }
        }
    }

    // epilogue (accumulators carry x1024 from weight pre-scale)
    int r4 = lane >> 2, c2 = (lane & 3) * 2;
    #pragma unroll
    for (int mt = 0; mt < 4; mt++) {
        #pragma unroll
        for (int half = 0; half < 2; half++) {
            int lr = wm + mt * 16 + r4 + half * 8;
            int grow = row0 + lr;
            if (grow >= rend) continue;
            int tok = s_rows[lr];
            #pragma unroll
            for (int j = 0; j < 4; j++) {
                int col = wn + j * 8 + c2;
                float v0 = d[mt][j][half * 2 + 0] * INV_WSCALE + s_bias[col];
                float v1 = d[mt][j][half * 2 + 1] * INV_WSCALE + s_bias[col + 1];
                if (FIRST) {
                    v0 = 0.5f * v0 * (1.0f + erff(v0 * 0.70710678118654752440f));
                    v1 = 0.5f * v1 * (1.0f + erff(v1 * 0.70710678118654752440f));
                    f16 h0, h1, l0, l1;
                    split2h(v0, h0, l0); split2h(v1, h1, l1);
                    *(uint32_t*)(g_hhi + (size_t)grow * NDIM + n0 + col) = pack2h(h0, h1);
                    *(uint32_t*)(g_hlo + (size_t)grow * NDIM + n0 + col) = pack2h(l0, l1);
                } else {
                    *(float2*)(Cout + (size_t)tok * NDIM + n0 + col) = make_float2(v0, v1);
                }
            }
        }
    }
}

// ---------------------------------------------------------------------------
extern "C" void kernel_launch(void* const* d_in, const int* in_sizes, int n_in,
                              void* d_out, int out_size)
{
    const float* x   = (const float*)d_in[0];
    const float* rw  = (const float*)d_in[1];
    const float* rb  = (const float*)d_in[2];
    const float* w1  = (const float*)d_in[3];
    const float* b1  = (const float*)d_in[4];
    const float* w2  = (const float*)d_in[5];
    const float* b2  = (const float*)d_in[6];
    const float* sw1 = (const float*)d_in[7];
    const float* sb1 = (const float*)d_in[8];
    const float* sw2 = (const float*)d_in[9];
    const float* sb2 = (const float*)d_in[10];
    float* out = (float*)d_out;

    cudaFuncSetAttribute(moe_gemm_mma<NH, NF, true>,
                         cudaFuncAttributeMaxDynamicSharedMemorySize, SMEMSZ);
    cudaFuncSetAttribute(moe_gemm_mma<NF, NH, false>,
                         cudaFuncAttributeMaxDynamicSharedMemorySize, SMEMSZ);

    // router + x split + fused w1 conversion
    router_kernel<<<NTOK + CVB_W, 256>>>(x, rw, rb, w1, sw1);
    assign_kernel<<<1, 320>>>();
    // GEMM1 (+ fused w2 conversion filling the tail wave): x @ w1 -> gelu -> g_h
    moe_gemm_mma<NH, NF, true ><<<dim3(NF / NTILE, TILE_Y + 18), 256, SMEMSZ>>>(
        b1, sb1, nullptr, w2, sw2);
    // GEMM2: g_h @ w2 -> scatter to out
    moe_gemm_mma<NF, NH, false><<<dim3(NH / NTILE, TILE_Y), 256, SMEMSZ>>>(
        b2, sb2, out, nullptr, nullptr);
}

// round 14
// speedup vs baseline: 2.0523x; 1.4862x over previous
#include <cuda_runtime.h>
#include <cuda_fp16.h>
#include <math.h>
#include <stdint.h>

// Problem constants
#define NH 1024
#define NF 4096
#define NE 8
#define NG 9                  // 8 experts + shared fallback
#define NTOK 4096
#define CAPE 512
#define MT 128                // M tile
#define NTILE 128             // N tile
#define KC 32                 // K chunk per stage
#define NSTAGE 3
#define TILE_Y 41             // max GEMM tile rows in grid.y
#define CVB_W 576             // converter blocks: 64 per group x 9 groups
#define WSCALE 1024.0f        // weight pre-scale (power of 2)
#define INV_WSCALE 0.0009765625f

// stage layout (bytes): A | B, each 8KB
//   A: [128 m][32 k] f16, row pitch 64B, chunk swizzle ch^(row&3)
//   B: [32 k][128 n] f16, row pitch 256B, chunk swizzle ch^(k&7)
#define A_OFF 0
#define B_OFF 8192
#define STAGE_BYTES 16384
#define SMEMSZ (1024 + NSTAGE*STAGE_BYTES)

typedef __half f16;

// ---------------- static device scratch ----------------
__device__ __align__(16) f16 g_x[(size_t)NTOK * NH];     // [token][k]
__device__ __align__(16) f16 g_w1[(size_t)NG * NH * NF]; // [g][k=H][n=F], x1024
__device__ __align__(16) f16 g_w2[(size_t)NG * NF * NH]; // [g][k=F][n=H], x1024
__device__ __align__(16) f16 g_h[(size_t)NTOK * NF];     // [grouped row][k]
__device__ int g_prim[NTOK];
__device__ int g_sec[NTOK];
__device__ int g_gather[NTOK];
__device__ int g_goff[NG + 1];
__device__ int g_ntiles;
__device__ int g_tile_group[64];
__device__ int g_tile_row[64];

// ---------------- helpers ----------------
__device__ __forceinline__ uint32_t smem_u32(const void* p) {
    uint32_t a;
    asm("{ .reg .u64 t; cvta.to.shared.u64 t, %1; cvt.u32.u64 %0, t; }" : "=r"(a) : "l"(p));
    return a;
}
__device__ __forceinline__ void cpasync16(uint32_t s, const void* g) {
    asm volatile("cp.async.cg.shared.global [%0], [%1], 16;" :: "r"(s), "l"(g) : "memory");
}
__device__ __forceinline__ void ldm4(uint32_t* r, uint32_t addr) {
    asm volatile("ldmatrix.sync.aligned.m8n8.x4.shared.b16 {%0,%1,%2,%3}, [%4];"
                 : "=r"(r[0]), "=r"(r[1]), "=r"(r[2]), "=r"(r[3]) : "r"(addr));
}
__device__ __forceinline__ void ldm4t(uint32_t* r, uint32_t addr) {
    asm volatile("ldmatrix.sync.aligned.m8n8.x4.trans.shared.b16 {%0,%1,%2,%3}, [%4];"
                 : "=r"(r[0]), "=r"(r[1]), "=r"(r[2]), "=r"(r[3]) : "r"(addr));
}
__device__ __forceinline__ void mma16816(float* d, const uint32_t* a, uint32_t b0, uint32_t b1) {
    asm volatile(
        "mma.sync.aligned.m16n8k16.row.col.f32.f16.f16.f32 "
        "{%0,%1,%2,%3}, {%4,%5,%6,%7}, {%8,%9}, {%0,%1,%2,%3};"
        : "+f"(d[0]), "+f"(d[1]), "+f"(d[2]), "+f"(d[3])
        : "r"(a[0]), "r"(a[1]), "r"(a[2]), "r"(a[3]), "r"(b0), "r"(b1));
}
// A-tile swizzle: 64B rows, 4 x 16B chunks/row
__device__ __forceinline__ uint32_t swA(int row, int ch) {
    return (uint32_t)((row * 4 + (ch ^ (row & 3))) << 4);
}
// B-tile swizzle: 256B rows, 16 x 16B chunks/row
__device__ __forceinline__ uint32_t swB(int krow, int ch) {
    return (uint32_t)((krow * 16 + (ch ^ (krow & 7))) << 4);
}
__device__ __forceinline__ uint32_t pack2h(f16 a, f16 b) {
    return (uint32_t)__half_as_ushort(a) | ((uint32_t)__half_as_ushort(b) << 16);
}

// Streaming fp32 -> fp16 (x1024) conversion of one 1/64 slice of one group's weights.
__device__ void convert_slice(const float* __restrict__ We, const float* __restrict__ Wf,
                              f16* __restrict__ Dst, int cvb, int tid)
{
    const size_t perg = (size_t)NH * NF;
    int g = cvb >> 6;
    int bid = cvb & 63;
    const float4* src = (const float4*)((g < NE) ? (We + (size_t)g * perg) : Wf);
    uint2* dh = (uint2*)(Dst + (size_t)g * perg);
    size_t n4 = perg / 4;
    for (size_t i = (size_t)bid * 256 + tid; i < n4; i += (size_t)64 * 256) {
        float4 v = src[i];
        f16 h0 = __float2half_rn(v.x * WSCALE);
        f16 h1 = __float2half_rn(v.y * WSCALE);
        f16 h2 = __float2half_rn(v.z * WSCALE);
        f16 h3 = __float2half_rn(v.w * WSCALE);
        dh[i] = make_uint2(pack2h(h0, h1), pack2h(h2, h3));
    }
}

// ---------------------------------------------------------------------------
// Router + x fp16 conversion + (fused) w1 conversion.
// ---------------------------------------------------------------------------
__global__ __launch_bounds__(256) void router_kernel(
    const float* __restrict__ x, const float* __restrict__ rw,
    const float* __restrict__ rb,
    const float* __restrict__ W1e, const float* __restrict__ W1f)
{
    if (blockIdx.x >= NTOK) {
        convert_slice(W1e, W1f, g_w1, blockIdx.x - NTOK, threadIdx.x);
        return;
    }
    int n = blockIdx.x;
    __shared__ float s_log[NE];
    int tid = threadIdx.x;
    int wid = tid >> 5, lane = tid & 31;
    const float* xr = x + (size_t)n * NH;

    {
        float4 v = ((const float4*)xr)[tid];
        f16 h0 = __float2half_rn(v.x), h1 = __float2half_rn(v.y);
        f16 h2 = __float2half_rn(v.z), h3 = __float2half_rn(v.w);
        ((uint2*)(g_x + (size_t)n * NH))[tid] = make_uint2(pack2h(h0, h1), pack2h(h2, h3));
    }

    const float* wr = rw + (size_t)wid * NH;
    float s = 0.f;
    #pragma unroll 8
    for (int k = lane; k < NH; k += 32) s += xr[k] * wr[k];
    #pragma unroll
    for (int o = 16; o; o >>= 1) s += __shfl_xor_sync(0xffffffffu, s, o);
    if (lane == 0) s_log[wid] = s + rb[wid];
    __syncthreads();
    if (tid == 0) {
        float b0 = -INFINITY; int i0 = 0;
        #pragma unroll
        for (int e = 0; e < NE; e++) { float v = s_log[e]; if (v > b0) { b0 = v; i0 = e; } }
        float b1 = -INFINITY; int i1 = 0;
        #pragma unroll
        for (int e = 0; e < NE; e++) { if (e == i0) continue; float v = s_log[e]; if (v > b1) { b1 = v; i1 = e; } }
        g_prim[n] = i0; g_sec[n] = i1;
    }
}

// ---------------------------------------------------------------------------
// Capacity assignment (exact reference semantics)
// ---------------------------------------------------------------------------
__global__ __launch_bounds__(320) void assign_kernel()
{
    __shared__ unsigned char s_prim[NTOK], s_sec[NTOK], s_keep[NTOK], s_assign[NTOK];
    __shared__ int s_used[NE], s_gcnt[NG], s_goff[NG + 1];
    int tid = threadIdx.x;
    int wid = tid >> 5, lane = tid & 31;
    unsigned lmask = (1u << lane) - 1u;

    for (int t = tid; t < NTOK; t += blockDim.x) {
        s_prim[t] = (unsigned char)g_prim[t];
        s_sec[t]  = (unsigned char)g_sec[t];
    }
    __syncthreads();

    if (wid < NE) {
        int e = wid, run = 0;
        for (int c = 0; c < NTOK; c += 32) {
            int t = c + lane;
            bool bit = (s_prim[t] == e);
            unsigned m = __ballot_sync(0xffffffffu, bit);
            if (bit) {
                int pos = run + __popc(m & lmask);
                bool keep = pos < CAPE;
                s_keep[t]   = keep ? 1 : 0;
                s_assign[t] = keep ? (unsigned char)e : (unsigned char)255;
            }
            run += __popc(m);
        }
        if (lane == 0) s_used[e] = run < CAPE ? run : CAPE;
    }
    __syncthreads();

    if (wid < NE) {
        int e = wid, run = 0, used = s_used[e];
        for (int c = 0; c < NTOK; c += 32) {
            int t = c + lane;
            bool bit = (s_sec[t] == e) && (s_keep[t] == 0);
            unsigned m = __ballot_sync(0xffffffffu, bit);
            if (bit) {
                int pos2 = run + __popc(m & lmask);
                bool take2 = (used + pos2) < CAPE;
                s_assign[t] = take2 ? (unsigned char)e : (unsigned char)8;
            }
            run += __popc(m);
        }
    }
    __syncthreads();

    if (wid < NG) {
        int g = wid, run = 0;
        for (int c = 0; c < NTOK; c += 32) {
            int t = c + lane;
            unsigned m = __ballot_sync(0xffffffffu, s_assign[t] == g);
            run += __popc(m);
        }
        if (lane == 0) s_gcnt[g] = run;
    }
    __syncthreads();

    if (tid == 0) {
        s_goff[0] = 0;
        for (int g = 0; g < NG; g++) s_goff[g + 1] = s_goff[g] + s_gcnt[g];
        int nt = 0;
        for (int g = 0; g < NG; g++)
            for (int r = s_goff[g]; r < s_goff[g + 1]; r += MT) {
                g_tile_group[nt] = g; g_tile_row[nt] = r; nt++;
            }
        g_ntiles = nt;
        for (int g = 0; g <= NG; g++) g_goff[g] = s_goff[g];
    }
    __syncthreads();

    if (wid < NG) {
        int g = wid, run = 0, base = s_goff[g];
        for (int c = 0; c < NTOK; c += 32) {
            int t = c + lane;
            bool bit = (s_assign[t] == g);
            unsigned m = __ballot_sync(0xffffffffu, bit);
            if (bit) g_gather[base + run + __popc(m & lmask)] = t;
            run += __popc(m);
        }
    }
}

// ---------------------------------------------------------------------------
// Grouped GEMM on mma.sync f16 single-pass, 128x128 tile, 8 warps,
// 3-stage cp.async pipeline, 2 CTAs/SM. Weights pre-scaled x1024.
// FIRST=true also carries fused w2 conversion blocks at blockIdx.y>=TILE_Y.
// ---------------------------------------------------------------------------
template<int KDIM, int NDIM, bool FIRST>
__global__ __launch_bounds__(256, 2) void moe_gemm_mma(
    const float* __restrict__ BiasE, const float* __restrict__ BiasF,
    float* __restrict__ Cout,
    const float* __restrict__ CWe, const float* __restrict__ CWf)
{
    constexpr int NCH = KDIM / KC;
    extern __shared__ __align__(1024) char smem[];

    if (FIRST && blockIdx.y >= TILE_Y) {
        int cvb = (blockIdx.y - TILE_Y) * 32 + blockIdx.x;   // 18*32 = 576
        if (cvb < CVB_W) convert_slice(CWe, CWf, g_w2, cvb, threadIdx.x);
        return;
    }

    int tileIdx = blockIdx.y;
    if (tileIdx >= g_ntiles) return;
    int tid = threadIdx.x, wid = tid >> 5, lane = tid & 31;
    int g    = g_tile_group[tileIdx];
    int row0 = g_tile_row[tileIdx];
    int rend = g_goff[g + 1];
    int n0   = blockIdx.x * NTILE;
    const float* bias = (g < NE) ? (BiasE + (size_t)g * NDIM) : BiasF;

    const f16* A = FIRST ? g_x : g_h;
    const f16* B = (FIRST ? g_w1 : g_w2) + (size_t)g * KDIM * NDIM;

    int*   s_rows = (int*)smem;            // 128 ints
    float* s_bias = (float*)(smem + 512);  // 128 floats
    uint32_t stage0 = smem_u32(smem) + 1024;

    if (tid < MT) {
        int r = row0 + tid;
        s_rows[tid] = (r < NTOK) ? g_gather[r] : 0;
        s_bias[tid] = bias[n0 + tid];
    }
    __syncthreads();

    auto load_stage = [&](int s, int c) {
        uint32_t st = stage0 + s * STAGE_BYTES;
        int k0 = c * KC;
        #pragma unroll
        for (int i = tid; i < 512; i += 256) {           // A: 512 chunks
            int row = i >> 2, ch = i & 3;
            int ar;
            if (FIRST) ar = s_rows[row];                 // token index
            else { ar = row0 + row; if (ar >= NTOK) ar = NTOK - 1; }
            const f16* src = A + (size_t)ar * KDIM + k0 + ch * 8;
            cpasync16(st + A_OFF + swA(row, ch), src);
        }
        #pragma unroll
        for (int i = tid; i < 512; i += 256) {           // B: [32 k][128 n]
            int kr = i >> 4, ch = i & 15;
            const f16* src = B + (size_t)(k0 + kr) * NDIM + n0 + ch * 8;
            cpasync16(st + B_OFF + swB(kr, ch), src);
        }
        asm volatile("cp.async.commit_group;" ::: "memory");
    };

    load_stage(0, 0);
    load_stage(1, 1);

    int wm = (wid >> 2) * 64;   // warp M offset
    int wn = (wid & 3) * 32;    // warp N offset

    // B ldmatrix.trans lane addressing
    int grp = lane >> 3, rit = lane & 7;
    int b_kadd = (grp & 1) * 8 + rit;
    int b_nsub = (grp >> 1) * 8;
    int a_r16 = lane & 15, a_chsel = lane >> 4;

    float d[4][4][4];
    #pragma unroll
    for (int a = 0; a < 4; a++)
        #pragma unroll
        for (int b = 0; b < 4; b++)
            #pragma unroll
            for (int c = 0; c < 4; c++) d[a][b][c] = 0.f;

    for (int c = 0; c < NCH; c++) {
        asm volatile("cp.async.wait_group 1;" ::: "memory");
        __syncthreads();
        if (c + 2 < NCH) load_stage((c + 2) % NSTAGE, c + 2);
        else asm volatile("cp.async.commit_group;" ::: "memory");

        uint32_t st = stage0 + (c % NSTAGE) * STAGE_BYTES;
        #pragma unroll
        for (int s = 0; s < 2; s++) {
            uint32_t bh[2][4];
            int kl = s * 16 + b_kadd;
            #pragma unroll
            for (int nt = 0; nt < 2; nt++) {
                int nch = (wn + nt * 16 + b_nsub) >> 3;
                ldm4t(bh[nt], st + B_OFF + swB(kl, nch));
            }
            int ach = s * 2 + a_chsel;
            #pragma unroll
            for (int mt = 0; mt < 4; mt++) {
                uint32_t ah[4];
                int row = wm + mt * 16 + a_r16;
                ldm4(ah, st + A_OFF + swA(row, ach));
                #pragma unroll
                for (int j = 0; j < 4; j++) {
                    int nt = j >> 1, sl = j & 1;
                    mma16816(d[mt][j], ah, bh[nt][sl * 2], bh[nt][sl * 2 + 1]);
                }
            }
        }
    }

    // epilogue (accumulators carry x1024 from weight pre-scale)
    int r4 = lane >> 2, c2 = (lane & 3) * 2;
    #pragma unroll
    for (int mt = 0; mt < 4; mt++) {
        #pragma unroll
        for (int half = 0; half < 2; half++) {
            int lr = wm + mt * 16 + r4 + half * 8;
            int grow = row0 + lr;
            if (grow >= rend) continue;
            int tok = s_rows[lr];
            #pragma unroll
            for (int j = 0; j < 4; j++) {
                int col = wn + j * 8 + c2;
                float v0 = d[mt][j][half * 2 + 0] * INV_WSCALE + s_bias[col];
                float v1 = d[mt][j][half * 2 + 1] * INV_WSCALE + s_bias[col + 1];
                if (FIRST) {
                    v0 = 0.5f * v0 * (1.0f + erff(v0 * 0.70710678118654752440f));
                    v1 = 0.5f * v1 * (1.0f + erff(v1 * 0.70710678118654752440f));
                    *(uint32_t*)(g_h + (size_t)grow * NDIM + n0 + col) =
                        pack2h(__float2half_rn(v0), __float2half_rn(v1));
                } else {
                    *(float2*)(Cout + (size_t)tok * NDIM + n0 + col) = make_float2(v0, v1);
                }
            }
        }
    }
}

// ---------------------------------------------------------------------------
extern "C" void kernel_launch(void* const* d_in, const int* in_sizes, int n_in,
                              void* d_out, int out_size)
{
    const float* x   = (const float*)d_in[0];
    const float* rw  = (const float*)d_in[1];
    const float* rb  = (const float*)d_in[2];
    const float* w1  = (const float*)d_in[3];
    const float* b1  = (const float*)d_in[4];
    const float* w2  = (const float*)d_in[5];
    const float* b2  = (const float*)d_in[6];
    const float* sw1 = (const float*)d_in[7];
    const float* sb1 = (const float*)d_in[8];
    const float* sw2 = (const float*)d_in[9];
    const float* sb2 = (const float*)d_in[10];
    float* out = (float*)d_out;

    cudaFuncSetAttribute(moe_gemm_mma<NH, NF, true>,
                         cudaFuncAttributeMaxDynamicSharedMemorySize, SMEMSZ);
    cudaFuncSetAttribute(moe_gemm_mma<NF, NH, false>,
                         cudaFuncAttributeMaxDynamicSharedMemorySize, SMEMSZ);

    // router + x conversion + fused w1 conversion
    router_kernel<<<NTOK + CVB_W, 256>>>(x, rw, rb, w1, sw1);
    assign_kernel<<<1, 320>>>();
    // GEMM1 (+ fused w2 conversion filling the tail wave): x @ w1 -> gelu -> g_h
    moe_gemm_mma<NH, NF, true ><<<dim3(NF / NTILE, TILE_Y + 18), 256, SMEMSZ>>>(
        b1, sb1, nullptr, w2, sw2);
    // GEMM2: g_h @ w2 -> scatter to out
    moe_gemm_mma<NF, NH, false><<<dim3(NH / NTILE, TILE_Y), 256, SMEMSZ>>>(
        b2, sb2, out, nullptr, nullptr);
}

// round 15
// speedup vs baseline: 2.2815x; 1.1117x over previous
#include <cuda_runtime.h>
#include <cuda_fp16.h>
#include <math.h>
#include <stdint.h>

// Problem constants
#define NH 1024
#define NF 4096
#define NE 8
#define NG 9                  // 8 experts + shared fallback
#define NTOK 4096
#define CAPE 512
#define MT 128                // M tile
#define NTILE 128             // N tile
#define KC 64                 // K chunk per stage (doubled: amortize barriers)
#define NSTAGE 3
#define TILE_Y 41             // max GEMM tile rows in grid.y
#define CVB_W 576             // converter blocks: 64 per group x 9 groups
#define WSCALE 1024.0f        // weight pre-scale (power of 2)
#define INV_WSCALE 0.0009765625f

// stage layout (bytes): A | B, each 16KB
//   A: [128 m][64 k] f16, row pitch 128B, chunk swizzle ch^(row&7)
//   B: [64 k][128 n] f16, row pitch 256B, chunk swizzle ch^(k&7)
#define A_OFF 0
#define B_OFF 16384
#define STAGE_BYTES 32768
#define SMEMSZ (1024 + NSTAGE*STAGE_BYTES)

typedef __half f16;

// ---------------- static device scratch ----------------
__device__ __align__(16) f16 g_x[(size_t)NTOK * NH];     // [token][k]
__device__ __align__(16) f16 g_w1[(size_t)NG * NH * NF]; // [g][k=H][n=F], x1024
__device__ __align__(16) f16 g_w2[(size_t)NG * NF * NH]; // [g][k=F][n=H], x1024
__device__ __align__(16) f16 g_h[(size_t)NTOK * NF];     // [grouped row][k]
__device__ int g_prim[NTOK];
__device__ int g_sec[NTOK];
__device__ int g_gather[NTOK];
__device__ int g_goff[NG + 1];
__device__ int g_ntiles;
__device__ int g_tile_group[64];
__device__ int g_tile_row[64];

// ---------------- helpers ----------------
__device__ __forceinline__ uint32_t smem_u32(const void* p) {
    uint32_t a;
    asm("{ .reg .u64 t; cvta.to.shared.u64 t, %1; cvt.u32.u64 %0, t; }" : "=r"(a) : "l"(p));
    return a;
}
__device__ __forceinline__ void cpasync16(uint32_t s, const void* g) {
    asm volatile("cp.async.cg.shared.global [%0], [%1], 16;" :: "r"(s), "l"(g) : "memory");
}
__device__ __forceinline__ void ldm4(uint32_t* r, uint32_t addr) {
    asm volatile("ldmatrix.sync.aligned.m8n8.x4.shared.b16 {%0,%1,%2,%3}, [%4];"
                 : "=r"(r[0]), "=r"(r[1]), "=r"(r[2]), "=r"(r[3]) : "r"(addr));
}
__device__ __forceinline__ void ldm4t(uint32_t* r, uint32_t addr) {
    asm volatile("ldmatrix.sync.aligned.m8n8.x4.trans.shared.b16 {%0,%1,%2,%3}, [%4];"
                 : "=r"(r[0]), "=r"(r[1]), "=r"(r[2]), "=r"(r[3]) : "r"(addr));
}
__device__ __forceinline__ void mma16816(float* d, const uint32_t* a, uint32_t b0, uint32_t b1) {
    asm volatile(
        "mma.sync.aligned.m16n8k16.row.col.f32.f16.f16.f32 "
        "{%0,%1,%2,%3}, {%4,%5,%6,%7}, {%8,%9}, {%0,%1,%2,%3};"
        : "+f"(d[0]), "+f"(d[1]), "+f"(d[2]), "+f"(d[3])
        : "r"(a[0]), "r"(a[1]), "r"(a[2]), "r"(a[3]), "r"(b0), "r"(b1));
}
// A-tile: 128B rows, 8 x 16B chunks/row, xor swizzle ch^(row&7)
__device__ __forceinline__ uint32_t swA(int row, int ch) {
    return (uint32_t)((row * 8 + (ch ^ (row & 7))) << 4);
}
// B-tile: 256B rows, 16 x 16B chunks/row, xor swizzle ch^(k&7)
__device__ __forceinline__ uint32_t swB(int krow, int ch) {
    return (uint32_t)((krow * 16 + (ch ^ (krow & 7))) << 4);
}
__device__ __forceinline__ uint32_t pack2h(f16 a, f16 b) {
    return (uint32_t)__half_as_ushort(a) | ((uint32_t)__half_as_ushort(b) << 16);
}

// Streaming fp32 -> fp16 (x1024) conversion of one 1/64 slice of one group's weights.
__device__ void convert_slice(const float* __restrict__ We, const float* __restrict__ Wf,
                              f16* __restrict__ Dst, int cvb, int tid)
{
    const size_t perg = (size_t)NH * NF;
    int g = cvb >> 6;
    int bid = cvb & 63;
    const float4* src = (const float4*)((g < NE) ? (We + (size_t)g * perg) : Wf);
    uint2* dh = (uint2*)(Dst + (size_t)g * perg);
    size_t n4 = perg / 4;
    for (size_t i = (size_t)bid * 256 + tid; i < n4; i += (size_t)64 * 256) {
        float4 v = src[i];
        f16 h0 = __float2half_rn(v.x * WSCALE);
        f16 h1 = __float2half_rn(v.y * WSCALE);
        f16 h2 = __float2half_rn(v.z * WSCALE);
        f16 h3 = __float2half_rn(v.w * WSCALE);
        dh[i] = make_uint2(pack2h(h0, h1), pack2h(h2, h3));
    }
}

// ---------------------------------------------------------------------------
// Router + x fp16 conversion + (fused) w1 conversion.
// ---------------------------------------------------------------------------
__global__ __launch_bounds__(256) void router_kernel(
    const float* __restrict__ x, const float* __restrict__ rw,
    const float* __restrict__ rb,
    const float* __restrict__ W1e, const float* __restrict__ W1f)
{
    if (blockIdx.x >= NTOK) {
        convert_slice(W1e, W1f, g_w1, blockIdx.x - NTOK, threadIdx.x);
        return;
    }
    int n = blockIdx.x;
    __shared__ float s_log[NE];
    int tid = threadIdx.x;
    int wid = tid >> 5, lane = tid & 31;
    const float* xr = x + (size_t)n * NH;

    {
        float4 v = ((const float4*)xr)[tid];
        f16 h0 = __float2half_rn(v.x), h1 = __float2half_rn(v.y);
        f16 h2 = __float2half_rn(v.z), h3 = __float2half_rn(v.w);
        ((uint2*)(g_x + (size_t)n * NH))[tid] = make_uint2(pack2h(h0, h1), pack2h(h2, h3));
    }

    const float* wr = rw + (size_t)wid * NH;
    float s = 0.f;
    #pragma unroll 8
    for (int k = lane; k < NH; k += 32) s += xr[k] * wr[k];
    #pragma unroll
    for (int o = 16; o; o >>= 1) s += __shfl_xor_sync(0xffffffffu, s, o);
    if (lane == 0) s_log[wid] = s + rb[wid];
    __syncthreads();
    if (tid == 0) {
        float b0 = -INFINITY; int i0 = 0;
        #pragma unroll
        for (int e = 0; e < NE; e++) { float v = s_log[e]; if (v > b0) { b0 = v; i0 = e; } }
        float b1 = -INFINITY; int i1 = 0;
        #pragma unroll
        for (int e = 0; e < NE; e++) { if (e == i0) continue; float v = s_log[e]; if (v > b1) { b1 = v; i1 = e; } }
        g_prim[n] = i0; g_sec[n] = i1;
    }
}

// ---------------------------------------------------------------------------
// Capacity assignment (exact reference semantics)
// ---------------------------------------------------------------------------
__global__ __launch_bounds__(320) void assign_kernel()
{
    __shared__ unsigned char s_prim[NTOK], s_sec[NTOK], s_keep[NTOK], s_assign[NTOK];
    __shared__ int s_used[NE], s_gcnt[NG], s_goff[NG + 1];
    int tid = threadIdx.x;
    int wid = tid >> 5, lane = tid & 31;
    unsigned lmask = (1u << lane) - 1u;

    for (int t = tid; t < NTOK; t += blockDim.x) {
        s_prim[t] = (unsigned char)g_prim[t];
        s_sec[t]  = (unsigned char)g_sec[t];
    }
    __syncthreads();

    if (wid < NE) {
        int e = wid, run = 0;
        for (int c = 0; c < NTOK; c += 32) {
            int t = c + lane;
            bool bit = (s_prim[t] == e);
            unsigned m = __ballot_sync(0xffffffffu, bit);
            if (bit) {
                int pos = run + __popc(m & lmask);
                bool keep = pos < CAPE;
                s_keep[t]   = keep ? 1 : 0;
                s_assign[t] = keep ? (unsigned char)e : (unsigned char)255;
            }
            run += __popc(m);
        }
        if (lane == 0) s_used[e] = run < CAPE ? run : CAPE;
    }
    __syncthreads();

    if (wid < NE) {
        int e = wid, run = 0, used = s_used[e];
        for (int c = 0; c < NTOK; c += 32) {
            int t = c + lane;
            bool bit = (s_sec[t] == e) && (s_keep[t] == 0);
            unsigned m = __ballot_sync(0xffffffffu, bit);
            if (bit) {
                int pos2 = run + __popc(m & lmask);
                bool take2 = (used + pos2) < CAPE;
                s_assign[t] = take2 ? (unsigned char)e : (unsigned char)8;
            }
            run += __popc(m);
        }
    }
    __syncthreads();

    if (wid < NG) {
        int g = wid, run = 0;
        for (int c = 0; c < NTOK; c += 32) {
            int t = c + lane;
            unsigned m = __ballot_sync(0xffffffffu, s_assign[t] == g);
            run += __popc(m);
        }
        if (lane == 0) s_gcnt[g] = run;
    }
    __syncthreads();

    if (tid == 0) {
        s_goff[0] = 0;
        for (int g = 0; g < NG; g++) s_goff[g + 1] = s_goff[g] + s_gcnt[g];
        int nt = 0;
        for (int g = 0; g < NG; g++)
            for (int r = s_goff[g]; r < s_goff[g + 1]; r += MT) {
                g_tile_group[nt] = g; g_tile_row[nt] = r; nt++;
            }
        g_ntiles = nt;
        for (int g = 0; g <= NG; g++) g_goff[g] = s_goff[g];
    }
    __syncthreads();

    if (wid < NG) {
        int g = wid, run = 0, base = s_goff[g];
        for (int c = 0; c < NTOK; c += 32) {
            int t = c + lane;
            bool bit = (s_assign[t] == g);
            unsigned m = __ballot_sync(0xffffffffu, bit);
            if (bit) g_gather[base + run + __popc(m & lmask)] = t;
            run += __popc(m);
        }
    }
}

// ---------------------------------------------------------------------------
// Grouped GEMM on mma.sync f16 single-pass, 128x128 tile, KC=64, 8 warps,
// 3-stage cp.async pipeline, 2 CTAs/SM. Weights pre-scaled x1024.
// FIRST=true also carries fused w2 conversion blocks at blockIdx.y>=TILE_Y.
// ---------------------------------------------------------------------------
template<int KDIM, int NDIM, bool FIRST>
__global__ __launch_bounds__(256, 2) void moe_gemm_mma(
    const float* __restrict__ BiasE, const float* __restrict__ BiasF,
    float* __restrict__ Cout,
    const float* __restrict__ CWe, const float* __restrict__ CWf)
{
    constexpr int NCH = KDIM / KC;
    extern __shared__ __align__(1024) char smem[];

    if (FIRST && blockIdx.y >= TILE_Y) {
        int cvb = (blockIdx.y - TILE_Y) * 32 + blockIdx.x;   // 18*32 = 576
        if (cvb < CVB_W) convert_slice(CWe, CWf, g_w2, cvb, threadIdx.x);
        return;
    }

    int tileIdx = blockIdx.y;
    if (tileIdx >= g_ntiles) return;
    int tid = threadIdx.x, wid = tid >> 5, lane = tid & 31;
    int g    = g_tile_group[tileIdx];
    int row0 = g_tile_row[tileIdx];
    int rend = g_goff[g + 1];
    int n0   = blockIdx.x * NTILE;
    const float* bias = (g < NE) ? (BiasE + (size_t)g * NDIM) : BiasF;

    const f16* A = FIRST ? g_x : g_h;
    const f16* B = (FIRST ? g_w1 : g_w2) + (size_t)g * KDIM * NDIM;

    int*   s_rows = (int*)smem;            // 128 ints
    float* s_bias = (float*)(smem + 512);  // 128 floats
    uint32_t stage0 = smem_u32(smem) + 1024;

    if (tid < MT) {
        int r = row0 + tid;
        s_rows[tid] = (r < NTOK) ? g_gather[r] : 0;
        s_bias[tid] = bias[n0 + tid];
    }
    __syncthreads();

    auto load_stage = [&](int s, int c) {
        uint32_t st = stage0 + s * STAGE_BYTES;
        int k0 = c * KC;
        #pragma unroll
        for (int i = tid; i < 1024; i += 256) {          // A: [128 m][64 k]
            int row = i >> 3, ch = i & 7;
            int ar;
            if (FIRST) ar = s_rows[row];                 // token index
            else { ar = row0 + row; if (ar >= NTOK) ar = NTOK - 1; }
            const f16* src = A + (size_t)ar * KDIM + k0 + ch * 8;
            cpasync16(st + A_OFF + swA(row, ch), src);
        }
        #pragma unroll
        for (int i = tid; i < 1024; i += 256) {          // B: [64 k][128 n]
            int kr = i >> 4, ch = i & 15;
            const f16* src = B + (size_t)(k0 + kr) * NDIM + n0 + ch * 8;
            cpasync16(st + B_OFF + swB(kr, ch), src);
        }
        asm volatile("cp.async.commit_group;" ::: "memory");
    };

    load_stage(0, 0);
    load_stage(1, 1);

    int wm = (wid >> 2) * 64;   // warp M offset
    int wn = (wid & 3) * 32;    // warp N offset

    // B ldmatrix.trans lane addressing
    int grp = lane >> 3, rit = lane & 7;
    int b_kadd = (grp & 1) * 8 + rit;
    int b_nsub = (grp >> 1) * 8;
    int a_r16 = lane & 15, a_chsel = lane >> 4;

    float d[4][4][4];
    #pragma unroll
    for (int a = 0; a < 4; a++)
        #pragma unroll
        for (int b = 0; b < 4; b++)
            #pragma unroll
            for (int c = 0; c < 4; c++) d[a][b][c] = 0.f;

    for (int c = 0; c < NCH; c++) {
        asm volatile("cp.async.wait_group 1;" ::: "memory");
        __syncthreads();
        if (c + 2 < NCH) load_stage((c + 2) % NSTAGE, c + 2);
        else asm volatile("cp.async.commit_group;" ::: "memory");

        uint32_t st = stage0 + (c % NSTAGE) * STAGE_BYTES;
        #pragma unroll
        for (int s = 0; s < 4; s++) {                   // 4 k16 substeps (KC=64)
            uint32_t bh[2][4];
            int kl = s * 16 + b_kadd;
            #pragma unroll
            for (int nt = 0; nt < 2; nt++) {
                int nch = (wn + nt * 16 + b_nsub) >> 3;
                ldm4t(bh[nt], st + B_OFF + swB(kl, nch));
            }
            int ach = s * 2 + a_chsel;
            #pragma unroll
            for (int mt = 0; mt < 4; mt++) {
                uint32_t ah[4];
                int row = wm + mt * 16 + a_r16;
                ldm4(ah, st + A_OFF + swA(row, ach));
                #pragma unroll
                for (int j = 0; j < 4; j++) {
                    int nt = j >> 1, sl = j & 1;
                    mma16816(d[mt][j], ah, bh[nt][sl * 2], bh[nt][sl * 2 + 1]);
                }
            }
        }
    }

    // epilogue (accumulators carry x1024 from weight pre-scale)
    int r4 = lane >> 2, c2 = (lane & 3) * 2;
    #pragma unroll
    for (int mt = 0; mt < 4; mt++) {
        #pragma unroll
        for (int half = 0; half < 2; half++) {
            int lr = wm + mt * 16 + r4 + half * 8;
            int grow = row0 + lr;
            if (grow >= rend) continue;
            int tok = s_rows[lr];
            #pragma unroll
            for (int j = 0; j < 4; j++) {
                int col = wn + j * 8 + c2;
                float v0 = d[mt][j][half * 2 + 0] * INV_WSCALE + s_bias[col];
                float v1 = d[mt][j][half * 2 + 1] * INV_WSCALE + s_bias[col + 1];
                if (FIRST) {
                    v0 = 0.5f * v0 * (1.0f + erff(v0 * 0.70710678118654752440f));
                    v1 = 0.5f * v1 * (1.0f + erff(v1 * 0.70710678118654752440f));
                    *(uint32_t*)(g_h + (size_t)grow * NDIM + n0 + col) =
                        pack2h(__float2half_rn(v0), __float2half_rn(v1));
                } else {
                    *(float2*)(Cout + (size_t)tok * NDIM + n0 + col) = make_float2(v0, v1);
                }
            }
        }
    }
}

// ---------------------------------------------------------------------------
extern "C" void kernel_launch(void* const* d_in, const int* in_sizes, int n_in,
                              void* d_out, int out_size)
{
    const float* x   = (const float*)d_in[0];
    const float* rw  = (const float*)d_in[1];
    const float* rb  = (const float*)d_in[2];
    const float* w1  = (const float*)d_in[3];
    const float* b1  = (const float*)d_in[4];
    const float* w2  = (const float*)d_in[5];
    const float* b2  = (const float*)d_in[6];
    const float* sw1 = (const float*)d_in[7];
    const float* sb1 = (const float*)d_in[8];
    const float* sw2 = (const float*)d_in[9];
    const float* sb2 = (const float*)d_in[10];
    float* out = (float*)d_out;

    cudaFuncSetAttribute(moe_gemm_mma<NH, NF, true>,
                         cudaFuncAttributeMaxDynamicSharedMemorySize, SMEMSZ);
    cudaFuncSetAttribute(moe_gemm_mma<NF, NH, false>,
                         cudaFuncAttributeMaxDynamicSharedMemorySize, SMEMSZ);

    // router + x conversion + fused w1 conversion
    router_kernel<<<NTOK + CVB_W, 256>>>(x, rw, rb, w1, sw1);
    assign_kernel<<<1, 320>>>();
    // GEMM1 (+ fused w2 conversion filling the tail wave): x @ w1 -> gelu -> g_h
    moe_gemm_mma<NH, NF, true ><<<dim3(NF / NTILE, TILE_Y + 18), 256, SMEMSZ>>>(
        b1, sb1, nullptr, w2, sw2);
    // GEMM2: g_h @ w2 -> scatter to out
    moe_gemm_mma<NF, NH, false><<<dim3(NH / NTILE, TILE_Y), 256, SMEMSZ>>>(
        b2, sb2, out, nullptr, nullptr);
}